// round 1
// baseline (speedup 1.0000x reference)
#include <cuda_runtime.h>

// Problem constants
#define DM   1024
#define NH   16
#define HD   64
#define BB   2
#define TT   2048

// Scratch (device globals: allocation-free rule)
// g_qkv layout: [which(3)][b][h][t][d]
__device__ float g_qkv[3 * BB * NH * TT * HD];
// g_att layout: [b][t][h][d]  == row-major [B*T, C]
__device__ float g_att[BB * TT * DM];

// ---------------------------------------------------------------------------
// SGEMM: C[M,N] = A[M,K] @ B[K,N] + bias[N]
// MODE 0: A = x param, epilogue scatters into g_qkv ([which][b][h][t][d])
// MODE 1: A = g_att (param ignored), epilogue writes plain row-major C
// BM=BN=128, BK=8, 256 threads, 8x8 per thread.
// ---------------------------------------------------------------------------
template <int MODE>
__global__ __launch_bounds__(256) void sgemm_k(const float* __restrict__ A,
                                               const float* __restrict__ Bw,
                                               const float* __restrict__ bias,
                                               float* __restrict__ C,
                                               int M, int N, int K)
{
    __shared__ float As[8][128];   // transposed A tile: As[k][m]
    __shared__ float Bs[8][128];   // Bs[k][n]

    const int tid = threadIdx.x;
    const int bm = blockIdx.y * 128;
    const int bn = blockIdx.x * 128;
    const int ty = tid >> 4;        // 0..15
    const int tx = tid & 15;        // 0..15

    const float* Aeff = (MODE == 0) ? A : (const float*)g_att;

    float acc[8][8];
#pragma unroll
    for (int i = 0; i < 8; i++)
#pragma unroll
        for (int j = 0; j < 8; j++) acc[i][j] = 0.f;

    const int arow = tid >> 1;          // 0..127
    const int acol = (tid & 1) * 4;     // 0 or 4
    const int brow = tid >> 5;          // 0..7
    const int bcol = (tid & 31) * 4;    // 0..124

    const float* Ap = Aeff + (bm + arow) * K + acol;
    const float* Bp = Bw + brow * N + bn + bcol;

    for (int k0 = 0; k0 < K; k0 += 8) {
        float4 a4 = *(const float4*)(Ap + k0);
        float4 b4 = *(const float4*)(Bp + k0 * N);
        As[acol + 0][arow] = a4.x;
        As[acol + 1][arow] = a4.y;
        As[acol + 2][arow] = a4.z;
        As[acol + 3][arow] = a4.w;
        *(float4*)&Bs[brow][bcol] = b4;
        __syncthreads();

#pragma unroll
        for (int k = 0; k < 8; k++) {
            float af[8], bf[8];
            *(float4*)(af)     = *(const float4*)&As[k][ty * 8];
            *(float4*)(af + 4) = *(const float4*)&As[k][ty * 8 + 4];
            *(float4*)(bf)     = *(const float4*)&Bs[k][tx * 8];
            *(float4*)(bf + 4) = *(const float4*)&Bs[k][tx * 8 + 4];
#pragma unroll
            for (int i = 0; i < 8; i++)
#pragma unroll
                for (int j = 0; j < 8; j++) acc[i][j] += af[i] * bf[j];
        }
        __syncthreads();
    }

    const int n0 = bn + tx * 8;
    float bb[8];
#pragma unroll
    for (int j = 0; j < 8; j++) bb[j] = bias[n0 + j];

    if (MODE == 0) {
        // n0..n0+7 lie in the same 64-wide (which,h) block (8 | 64)
        const int which = n0 >> 10;
        const int rem   = n0 & 1023;
        const int h     = rem >> 6;
        const int d     = rem & 63;
#pragma unroll
        for (int i = 0; i < 8; i++) {
            const int m = bm + ty * 8 + i;
            const int b = m >> 11;
            const int t = m & 2047;
            float* dst = g_qkv + ((((which * BB + b) * NH + h) * TT + t) * HD + d);
#pragma unroll
            for (int j = 0; j < 8; j++) dst[j] = acc[i][j] + bb[j];
        }
    } else {
#pragma unroll
        for (int i = 0; i < 8; i++) {
            const int m = bm + ty * 8 + i;
            float* dst = C + m * N + n0;
#pragma unroll
            for (int j = 0; j < 8; j++) dst[j] = acc[i][j] + bb[j];
        }
    }
}

// ---------------------------------------------------------------------------
// Flash attention (causal, online softmax), fp32.
// 64 query rows x 64 keys per tile, Dh=64. 256 threads = 16x16, 4x4 per thread.
// Q,K stored transposed in smem [d][r] with XOR swizzle to kill transpose-store
// bank conflicts; V row-major [s][d]; P reuses the K buffer.
// ---------------------------------------------------------------------------
__device__ __forceinline__ int SW(int d, int r) {
    // swizzled transposed index: stride 64, column r xor'd by bits of d
    return d * 64 + (r ^ (((d >> 2) & 7) << 2));
}

__global__ __launch_bounds__(256) void flash_k()
{
    extern __shared__ float smem[];
    float* Qs = smem;           // 4096 floats, swizzled [d][r]
    float* KP = smem + 4096;    // K transposed swizzled, then P row-major
    float* Vs = smem + 8192;    // [s][d], plain

    const int tid = threadIdx.x;
    const int qt = blockIdx.x;  // query tile 0..31
    const int h  = blockIdx.y;
    const int b  = blockIdx.z;
    const int ty = tid >> 4;    // 0..15
    const int tx = tid & 15;    // 0..15
    const float scale = 0.125f; // 1/sqrt(64)

    const float* Qg = g_qkv + (((0 * BB + b) * NH + h) * TT) * HD;
    const float* Kg = g_qkv + (((1 * BB + b) * NH + h) * TT) * HD;
    const float* Vg = g_qkv + (((2 * BB + b) * NH + h) * TT) * HD;

    const int lr = tid >> 4;        // 0..15
    const int lc = (tid & 15) * 4;  // 0..60

    // Load Q tile, transposed + swizzled
#pragma unroll
    for (int it = 0; it < 4; it++) {
        const int r = lr + it * 16;
        float4 v = *(const float4*)(Qg + (qt * 64 + r) * HD + lc);
        Qs[SW(lc + 0, r)] = v.x;
        Qs[SW(lc + 1, r)] = v.y;
        Qs[SW(lc + 2, r)] = v.z;
        Qs[SW(lc + 3, r)] = v.w;
    }

    float m_i[4], l_i[4], acc[4][4];
#pragma unroll
    for (int i = 0; i < 4; i++) {
        m_i[i] = -1e30f;
        l_i[i] = 0.f;
#pragma unroll
        for (int j = 0; j < 4; j++) acc[i][j] = 0.f;
    }

    for (int nt = 0; nt <= qt; nt++) {
        __syncthreads();  // previous PV reads of KP/Vs done; Q writes visible
        // Load K tile transposed + swizzled, V tile row-major
#pragma unroll
        for (int it = 0; it < 4; it++) {
            const int r = lr + it * 16;
            float4 kv = *(const float4*)(Kg + (nt * 64 + r) * HD + lc);
            KP[SW(lc + 0, r)] = kv.x;
            KP[SW(lc + 1, r)] = kv.y;
            KP[SW(lc + 2, r)] = kv.z;
            KP[SW(lc + 3, r)] = kv.w;
            float4 vv = *(const float4*)(Vg + (nt * 64 + r) * HD + lc);
            *(float4*)&Vs[r * 64 + lc] = vv;
        }
        __syncthreads();

        // S = Q @ K^T
        float s[4][4];
#pragma unroll
        for (int i = 0; i < 4; i++)
#pragma unroll
            for (int j = 0; j < 4; j++) s[i][j] = 0.f;
#pragma unroll
        for (int d = 0; d < 64; d++) {
            float aq[4], bk[4];
            *(float4*)aq = *(const float4*)&Qs[SW(d, ty * 4)];
            *(float4*)bk = *(const float4*)&KP[SW(d, tx * 4)];
#pragma unroll
            for (int i = 0; i < 4; i++)
#pragma unroll
                for (int j = 0; j < 4; j++) s[i][j] += aq[i] * bk[j];
        }

        // scale + causal mask + local row max
        const bool diag = (nt == qt);
        float mloc[4];
#pragma unroll
        for (int i = 0; i < 4; i++) {
            mloc[i] = -1e30f;
#pragma unroll
            for (int j = 0; j < 4; j++) {
                float v = s[i][j] * scale;
                if (diag && (tx * 4 + j) > (ty * 4 + i)) v = -1e30f;
                s[i][j] = v;
                mloc[i] = fmaxf(mloc[i], v);
            }
        }
        // reduce max across the 16 lanes of this row group (xor 1,2,4,8)
#pragma unroll
        for (int off = 8; off > 0; off >>= 1)
#pragma unroll
            for (int i = 0; i < 4; i++)
                mloc[i] = fmaxf(mloc[i], __shfl_xor_sync(0xffffffffu, mloc[i], off));

        float pl[4];
#pragma unroll
        for (int i = 0; i < 4; i++) {
            const float mn = fmaxf(m_i[i], mloc[i]);
            const float f  = __expf(m_i[i] - mn);
            m_i[i] = mn;
            float sum = 0.f;
#pragma unroll
            for (int j = 0; j < 4; j++) {
                float p = __expf(s[i][j] - mn);
                s[i][j] = p;
                sum += p;
            }
            pl[i] = sum;
            l_i[i] *= f;
#pragma unroll
            for (int j = 0; j < 4; j++) acc[i][j] *= f;
        }
#pragma unroll
        for (int off = 8; off > 0; off >>= 1)
#pragma unroll
            for (int i = 0; i < 4; i++)
                pl[i] += __shfl_xor_sync(0xffffffffu, pl[i], off);
#pragma unroll
        for (int i = 0; i < 4; i++) l_i[i] += pl[i];

        __syncthreads();  // all K-transposed reads done before P overwrites
        // write P (row-major, plain stride 64; contiguous per half-warp)
#pragma unroll
        for (int i = 0; i < 4; i++)
            *(float4*)&KP[(ty * 4 + i) * 64 + tx * 4] = *(float4*)s[i];
        __syncthreads();

        // acc += P @ V
#pragma unroll
        for (int n = 0; n < 64; n++) {
            float pa[4], vv[4];
#pragma unroll
            for (int i = 0; i < 4; i++) pa[i] = KP[(ty * 4 + i) * 64 + n];
            *(float4*)vv = *(const float4*)&Vs[n * 64 + tx * 4];
#pragma unroll
            for (int i = 0; i < 4; i++)
#pragma unroll
                for (int j = 0; j < 4; j++) acc[i][j] += pa[i] * vv[j];
        }
    }

    // epilogue: divide by l, write [b][t][h][d]
#pragma unroll
    for (int i = 0; i < 4; i++) {
        const float inv = 1.0f / l_i[i];
        const int t = qt * 64 + ty * 4 + i;
        float4 o;
        o.x = acc[i][0] * inv;
        o.y = acc[i][1] * inv;
        o.z = acc[i][2] * inv;
        o.w = acc[i][3] * inv;
        *(float4*)&g_att[((b * TT + t) * NH + h) * HD + tx * 4] = o;
    }
}

// ---------------------------------------------------------------------------
// kernel_launch
// ---------------------------------------------------------------------------
extern "C" void kernel_launch(void* const* d_in, const int* in_sizes, int n_in,
                              void* d_out, int out_size)
{
    const float* x      = (const float*)d_in[0];
    const float* w_qkv  = (const float*)d_in[1];
    const float* b_qkv  = (const float*)d_in[2];
    const float* w_proj = (const float*)d_in[3];
    const float* b_proj = (const float*)d_in[4];
    float* out = (float*)d_out;

    const int M = BB * TT;  // 4096

    // 1) QKV projection: [4096,1024] @ [1024,3072] + bias -> g_qkv scatter
    {
        dim3 grid(3 * DM / 128, M / 128);  // (24, 32)
        sgemm_k<0><<<grid, 256>>>(x, w_qkv, b_qkv, nullptr, M, 3 * DM, DM);
    }

    // 2) Causal flash attention -> g_att
    {
        cudaFuncSetAttribute(flash_k, cudaFuncAttributeMaxDynamicSharedMemorySize,
                             3 * 64 * 64 * (int)sizeof(float));
        dim3 grid(TT / 64, NH, BB);  // (32, 16, 2)
        flash_k<<<grid, 256, 3 * 64 * 64 * sizeof(float)>>>();
    }

    // 3) Output projection: g_att[4096,1024] @ [1024,1024] + bias -> out
    {
        dim3 grid(DM / 128, M / 128);  // (8, 32)
        sgemm_k<1><<<grid, 256>>>(nullptr, w_proj, b_proj, out, M, DM, DM);
    }
}

// round 3
// speedup vs baseline: 1.5596x; 1.5596x over previous
#include <cuda_runtime.h>
#include <cstdint>

// Problem constants
#define DM   1024
#define NH   16
#define HD   64
#define BB   2
#define TT   2048

// Scratch (device globals: allocation-free rule)
__device__ float g_qkv[3 * BB * NH * TT * HD];   // [which][b][h][t][d]
__device__ float g_att[BB * TT * DM];            // [b][t][h][d] == [B*T, C]

// ---------------------------------------------------------------------------
// tf32 helpers (portable PTX: works on plain sm_103 target)
// ---------------------------------------------------------------------------
__device__ __forceinline__ float to_tf32(float x) {
    uint32_t u;
    asm("cvt.rna.tf32.f32 %0, %1;" : "=r"(u) : "f"(x));
    return __uint_as_float(u);
}

__device__ __forceinline__ void mma_tf32(float& c0, float& c1, float& c2, float& c3,
                                         uint32_t a0, uint32_t a1, uint32_t a2, uint32_t a3,
                                         uint32_t b0, uint32_t b1) {
    asm volatile(
        "mma.sync.aligned.m16n8k8.row.col.f32.tf32.tf32.f32 "
        "{%0,%1,%2,%3}, {%4,%5,%6,%7}, {%8,%9}, {%0,%1,%2,%3};"
        : "+f"(c0), "+f"(c1), "+f"(c2), "+f"(c3)
        : "r"(a0), "r"(a1), "r"(a2), "r"(a3), "r"(b0), "r"(b1));
}

// ---------------------------------------------------------------------------
// tf32 tensor-core GEMM: C[M,N] = A[M,K] @ B[K,N] + bias[N]
// BM=BN=128, BK=16, 256 threads = 8 warps (4 m-warps x 2 n-warps),
// each warp 32x64 via m16n8k8 mma.sync. B consumed directly (k,n) row-major.
// MODE 0: A = x, epilogue scatters into g_qkv.  MODE 1: A = g_att, plain C.
// ---------------------------------------------------------------------------
template <int MODE>
__global__ __launch_bounds__(256) void mma_gemm(const float* __restrict__ A,
                                                const float* __restrict__ Bw,
                                                const float* __restrict__ bias,
                                                float* __restrict__ C,
                                                int M, int N, int K)
{
    // pads chosen so fragment LDS patterns are bank-conflict-free
    __shared__ float As[2][128][20];   // [m][k], 20-float rows
    __shared__ float Bs[2][16][136];   // [k][n], 136-float rows

    const int tid  = threadIdx.x;
    const int bm   = blockIdx.y * 128;
    const int bn   = blockIdx.x * 128;
    const int w    = tid >> 5;
    const int lane = tid & 31;
    const int g    = lane >> 2;   // groupID
    const int t    = lane & 3;    // threadID_in_group
    const int m0   = (w & 3) * 32;   // warp m offset
    const int n0   = (w >> 2) * 64;  // warp n offset

    const float* Aeff = (MODE == 0) ? A : (const float*)g_att;

    float acc[2][8][4];
#pragma unroll
    for (int mt = 0; mt < 2; mt++)
#pragma unroll
        for (int nt = 0; nt < 8; nt++)
#pragma unroll
            for (int r = 0; r < 4; r++) acc[mt][nt][r] = 0.f;

    // global-load indexing: A tile 128x16, B tile 16x128, 8 floats/thread each
    const int arow = tid >> 1;            // 0..127
    const int acol = (tid & 1) * 8;       // 0 or 8
    const int brow = tid >> 4;            // 0..15
    const int bcol = (tid & 15) * 8;      // 0..120

    const float* Ap = Aeff + (size_t)(bm + arow) * K + acol;
    const float* Bp = Bw + (size_t)brow * N + bn + bcol;

    float4 pa0 = *(const float4*)(Ap);
    float4 pa1 = *(const float4*)(Ap + 4);
    float4 pb0 = *(const float4*)(Bp);
    float4 pb1 = *(const float4*)(Bp + 4);

    const int NC = K >> 4;   // chunks of 16

    for (int c = 0; c < NC; c++) {
        const int st = c & 1;
        {   // store (tf32-rounded) to smem
            float4 ca0, ca1, cb0, cb1;
            ca0.x = to_tf32(pa0.x); ca0.y = to_tf32(pa0.y);
            ca0.z = to_tf32(pa0.z); ca0.w = to_tf32(pa0.w);
            ca1.x = to_tf32(pa1.x); ca1.y = to_tf32(pa1.y);
            ca1.z = to_tf32(pa1.z); ca1.w = to_tf32(pa1.w);
            cb0.x = to_tf32(pb0.x); cb0.y = to_tf32(pb0.y);
            cb0.z = to_tf32(pb0.z); cb0.w = to_tf32(pb0.w);
            cb1.x = to_tf32(pb1.x); cb1.y = to_tf32(pb1.y);
            cb1.z = to_tf32(pb1.z); cb1.w = to_tf32(pb1.w);
            *(float4*)&As[st][arow][acol]     = ca0;
            *(float4*)&As[st][arow][acol + 4] = ca1;
            *(float4*)&Bs[st][brow][bcol]     = cb0;
            *(float4*)&Bs[st][brow][bcol + 4] = cb1;
        }
        __syncthreads();

        if (c + 1 < NC) {   // prefetch next chunk
            const int k0 = (c + 1) << 4;
            pa0 = *(const float4*)(Ap + k0);
            pa1 = *(const float4*)(Ap + k0 + 4);
            pb0 = *(const float4*)(Bp + (size_t)k0 * N);
            pb1 = *(const float4*)(Bp + (size_t)k0 * N + 4);
        }

#pragma unroll
        for (int ks = 0; ks < 2; ks++) {
            const int kb = ks * 8;
            uint32_t af[2][4], bf[8][2];
#pragma unroll
            for (int mt = 0; mt < 2; mt++) {
                const int m = m0 + mt * 16 + g;
                af[mt][0] = __float_as_uint(As[st][m][kb + t]);
                af[mt][1] = __float_as_uint(As[st][m + 8][kb + t]);
                af[mt][2] = __float_as_uint(As[st][m][kb + t + 4]);
                af[mt][3] = __float_as_uint(As[st][m + 8][kb + t + 4]);
            }
#pragma unroll
            for (int nt = 0; nt < 8; nt++) {
                const int n = n0 + nt * 8 + g;
                bf[nt][0] = __float_as_uint(Bs[st][kb + t][n]);
                bf[nt][1] = __float_as_uint(Bs[st][kb + t + 4][n]);
            }
#pragma unroll
            for (int mt = 0; mt < 2; mt++)
#pragma unroll
                for (int nt = 0; nt < 8; nt++)
                    mma_tf32(acc[mt][nt][0], acc[mt][nt][1],
                             acc[mt][nt][2], acc[mt][nt][3],
                             af[mt][0], af[mt][1], af[mt][2], af[mt][3],
                             bf[nt][0], bf[nt][1]);
        }
        __syncthreads();
    }

    // ---- epilogue ----
    const int ng = bn + n0;   // 64-aligned warp n base
    if (MODE == 0) {
        const int which = ng >> 10;
        const int rem   = ng & 1023;
        const int h     = rem >> 6;
#pragma unroll
        for (int mt = 0; mt < 2; mt++) {
            const int row0 = bm + m0 + mt * 16 + g;
            const int row1 = row0 + 8;
            const int b0i = row0 >> 11, t0i = row0 & 2047;
            const int b1i = row1 >> 11, t1i = row1 & 2047;
            float* base0 = g_qkv + ((size_t)((which * BB + b0i) * NH + h) * TT + t0i) * HD;
            float* base1 = g_qkv + ((size_t)((which * BB + b1i) * NH + h) * TT + t1i) * HD;
#pragma unroll
            for (int nt = 0; nt < 8; nt++) {
                const int d = nt * 8 + 2 * t;
                const float bx = bias[ng + d], by = bias[ng + d + 1];
                float2 o0 = { acc[mt][nt][0] + bx, acc[mt][nt][1] + by };
                float2 o1 = { acc[mt][nt][2] + bx, acc[mt][nt][3] + by };
                *(float2*)(base0 + d) = o0;
                *(float2*)(base1 + d) = o1;
            }
        }
    } else {
#pragma unroll
        for (int mt = 0; mt < 2; mt++) {
            const int row0 = bm + m0 + mt * 16 + g;
            const int row1 = row0 + 8;
#pragma unroll
            for (int nt = 0; nt < 8; nt++) {
                const int n = ng + nt * 8 + 2 * t;
                const float bx = bias[n], by = bias[n + 1];
                float2 o0 = { acc[mt][nt][0] + bx, acc[mt][nt][1] + by };
                float2 o1 = { acc[mt][nt][2] + bx, acc[mt][nt][3] + by };
                *(float2*)(C + (size_t)row0 * N + n) = o0;
                *(float2*)(C + (size_t)row1 * N + n) = o1;
            }
        }
    }
}

// ---------------------------------------------------------------------------
// Flash attention (causal, online softmax), fp32 — unchanged from R1.
// ---------------------------------------------------------------------------
__device__ __forceinline__ int SW(int d, int r) {
    return d * 64 + (r ^ (((d >> 2) & 7) << 2));
}

__global__ __launch_bounds__(256) void flash_k()
{
    extern __shared__ float smemf[];
    float* Qs = smemf;
    float* KP = smemf + 4096;
    float* Vs = smemf + 8192;

    const int tid = threadIdx.x;
    const int qt = blockIdx.x;
    const int h  = blockIdx.y;
    const int b  = blockIdx.z;
    const int ty = tid >> 4;
    const int tx = tid & 15;
    const float scale = 0.125f;

    const float* Qg = g_qkv + (((0 * BB + b) * NH + h) * TT) * HD;
    const float* Kg = g_qkv + (((1 * BB + b) * NH + h) * TT) * HD;
    const float* Vg = g_qkv + (((2 * BB + b) * NH + h) * TT) * HD;

    const int lr = tid >> 4;
    const int lc = (tid & 15) * 4;

#pragma unroll
    for (int it = 0; it < 4; it++) {
        const int r = lr + it * 16;
        float4 v = *(const float4*)(Qg + (qt * 64 + r) * HD + lc);
        Qs[SW(lc + 0, r)] = v.x;
        Qs[SW(lc + 1, r)] = v.y;
        Qs[SW(lc + 2, r)] = v.z;
        Qs[SW(lc + 3, r)] = v.w;
    }

    float m_i[4], l_i[4], acc[4][4];
#pragma unroll
    for (int i = 0; i < 4; i++) {
        m_i[i] = -1e30f; l_i[i] = 0.f;
#pragma unroll
        for (int j = 0; j < 4; j++) acc[i][j] = 0.f;
    }

    for (int nt = 0; nt <= qt; nt++) {
        __syncthreads();
#pragma unroll
        for (int it = 0; it < 4; it++) {
            const int r = lr + it * 16;
            float4 kv = *(const float4*)(Kg + (nt * 64 + r) * HD + lc);
            KP[SW(lc + 0, r)] = kv.x;
            KP[SW(lc + 1, r)] = kv.y;
            KP[SW(lc + 2, r)] = kv.z;
            KP[SW(lc + 3, r)] = kv.w;
            float4 vv = *(const float4*)(Vg + (nt * 64 + r) * HD + lc);
            *(float4*)&Vs[r * 64 + lc] = vv;
        }
        __syncthreads();

        float s[4][4];
#pragma unroll
        for (int i = 0; i < 4; i++)
#pragma unroll
            for (int j = 0; j < 4; j++) s[i][j] = 0.f;
#pragma unroll
        for (int d = 0; d < 64; d++) {
            float aq[4], bk[4];
            *(float4*)aq = *(const float4*)&Qs[SW(d, ty * 4)];
            *(float4*)bk = *(const float4*)&KP[SW(d, tx * 4)];
#pragma unroll
            for (int i = 0; i < 4; i++)
#pragma unroll
                for (int j = 0; j < 4; j++) s[i][j] += aq[i] * bk[j];
        }

        const bool diag = (nt == qt);
        float mloc[4];
#pragma unroll
        for (int i = 0; i < 4; i++) {
            mloc[i] = -1e30f;
#pragma unroll
            for (int j = 0; j < 4; j++) {
                float v = s[i][j] * scale;
                if (diag && (tx * 4 + j) > (ty * 4 + i)) v = -1e30f;
                s[i][j] = v;
                mloc[i] = fmaxf(mloc[i], v);
            }
        }
#pragma unroll
        for (int off = 8; off > 0; off >>= 1)
#pragma unroll
            for (int i = 0; i < 4; i++)
                mloc[i] = fmaxf(mloc[i], __shfl_xor_sync(0xffffffffu, mloc[i], off));

        float pl[4];
#pragma unroll
        for (int i = 0; i < 4; i++) {
            const float mn = fmaxf(m_i[i], mloc[i]);
            const float f  = __expf(m_i[i] - mn);
            m_i[i] = mn;
            float sum = 0.f;
#pragma unroll
            for (int j = 0; j < 4; j++) {
                float p = __expf(s[i][j] - mn);
                s[i][j] = p;
                sum += p;
            }
            pl[i] = sum;
            l_i[i] *= f;
#pragma unroll
            for (int j = 0; j < 4; j++) acc[i][j] *= f;
        }
#pragma unroll
        for (int off = 8; off > 0; off >>= 1)
#pragma unroll
            for (int i = 0; i < 4; i++)
                pl[i] += __shfl_xor_sync(0xffffffffu, pl[i], off);
#pragma unroll
        for (int i = 0; i < 4; i++) l_i[i] += pl[i];

        __syncthreads();
#pragma unroll
        for (int i = 0; i < 4; i++)
            *(float4*)&KP[(ty * 4 + i) * 64 + tx * 4] = *(float4*)s[i];
        __syncthreads();

#pragma unroll
        for (int n = 0; n < 64; n++) {
            float pa[4], vv[4];
#pragma unroll
            for (int i = 0; i < 4; i++) pa[i] = KP[(ty * 4 + i) * 64 + n];
            *(float4*)vv = *(const float4*)&Vs[n * 64 + tx * 4];
#pragma unroll
            for (int i = 0; i < 4; i++)
#pragma unroll
                for (int j = 0; j < 4; j++) acc[i][j] += pa[i] * vv[j];
        }
    }

#pragma unroll
    for (int i = 0; i < 4; i++) {
        const float inv = 1.0f / l_i[i];
        const int t = qt * 64 + ty * 4 + i;
        float4 o;
        o.x = acc[i][0] * inv;
        o.y = acc[i][1] * inv;
        o.z = acc[i][2] * inv;
        o.w = acc[i][3] * inv;
        *(float4*)&g_att[((b * TT + t) * NH + h) * HD + tx * 4] = o;
    }
}

// ---------------------------------------------------------------------------
// kernel_launch
// ---------------------------------------------------------------------------
extern "C" void kernel_launch(void* const* d_in, const int* in_sizes, int n_in,
                              void* d_out, int out_size)
{
    const float* x      = (const float*)d_in[0];
    const float* w_qkv  = (const float*)d_in[1];
    const float* b_qkv  = (const float*)d_in[2];
    const float* w_proj = (const float*)d_in[3];
    const float* b_proj = (const float*)d_in[4];
    float* out = (float*)d_out;

    const int M = BB * TT;  // 4096

    cudaFuncSetAttribute(flash_k, cudaFuncAttributeMaxDynamicSharedMemorySize,
                         3 * 64 * 64 * (int)sizeof(float));

    // 1) QKV projection (tf32 mma.sync): [4096,1024] @ [1024,3072] -> g_qkv
    mma_gemm<0><<<dim3(3 * DM / 128, M / 128), 256>>>(x, w_qkv, b_qkv, nullptr, M, 3 * DM, DM);

    // 2) causal flash attention -> g_att
    flash_k<<<dim3(TT / 64, NH, BB), 256, 3 * 64 * 64 * sizeof(float)>>>();

    // 3) output projection (tf32 mma.sync) -> out
    mma_gemm<1><<<dim3(DM / 128, M / 128), 256>>>(nullptr, w_proj, b_proj, out, M, DM, DM);
}

// round 4
// speedup vs baseline: 2.4053x; 1.5423x over previous
#include <cuda_runtime.h>
#include <cstdint>

// Problem constants
#define DM   1024
#define NH   16
#define HD   64
#define BB   2
#define TT   2048

// Scratch (device globals: allocation-free rule)
__device__ float g_qkv[3 * BB * NH * TT * HD];   // [which][b][h][t][d]
__device__ float g_att[BB * TT * DM];            // [b][t][h][d] == [B*T, C]

// ---------------------------------------------------------------------------
// tf32 helpers (portable PTX: works on plain sm_103 target)
// ---------------------------------------------------------------------------
__device__ __forceinline__ float to_tf32(float x) {
    uint32_t u;
    asm("cvt.rna.tf32.f32 %0, %1;" : "=r"(u) : "f"(x));
    return __uint_as_float(u);
}

__device__ __forceinline__ void mma_tf32(float& c0, float& c1, float& c2, float& c3,
                                         uint32_t a0, uint32_t a1, uint32_t a2, uint32_t a3,
                                         uint32_t b0, uint32_t b1) {
    asm volatile(
        "mma.sync.aligned.m16n8k8.row.col.f32.tf32.tf32.f32 "
        "{%0,%1,%2,%3}, {%4,%5,%6,%7}, {%8,%9}, {%0,%1,%2,%3};"
        : "+f"(c0), "+f"(c1), "+f"(c2), "+f"(c3)
        : "r"(a0), "r"(a1), "r"(a2), "r"(a3), "r"(b0), "r"(b1));
}

// ---------------------------------------------------------------------------
// tf32 tensor-core GEMM: C[M,N] = A[M,K] @ B[K,N] + bias[N]
// (unchanged from R3 — 128x128 tile, BK=16, 8 warps, 32x64 per warp)
// ---------------------------------------------------------------------------
template <int MODE>
__global__ __launch_bounds__(256) void mma_gemm(const float* __restrict__ A,
                                                const float* __restrict__ Bw,
                                                const float* __restrict__ bias,
                                                float* __restrict__ C,
                                                int M, int N, int K)
{
    __shared__ float As[2][128][20];
    __shared__ float Bs[2][16][136];

    const int tid  = threadIdx.x;
    const int bm   = blockIdx.y * 128;
    const int bn   = blockIdx.x * 128;
    const int w    = tid >> 5;
    const int lane = tid & 31;
    const int g    = lane >> 2;
    const int t    = lane & 3;
    const int m0   = (w & 3) * 32;
    const int n0   = (w >> 2) * 64;

    const float* Aeff = (MODE == 0) ? A : (const float*)g_att;

    float acc[2][8][4];
#pragma unroll
    for (int mt = 0; mt < 2; mt++)
#pragma unroll
        for (int nt = 0; nt < 8; nt++)
#pragma unroll
            for (int r = 0; r < 4; r++) acc[mt][nt][r] = 0.f;

    const int arow = tid >> 1;
    const int acol = (tid & 1) * 8;
    const int brow = tid >> 4;
    const int bcol = (tid & 15) * 8;

    const float* Ap = Aeff + (size_t)(bm + arow) * K + acol;
    const float* Bp = Bw + (size_t)brow * N + bn + bcol;

    float4 pa0 = *(const float4*)(Ap);
    float4 pa1 = *(const float4*)(Ap + 4);
    float4 pb0 = *(const float4*)(Bp);
    float4 pb1 = *(const float4*)(Bp + 4);

    const int NC = K >> 4;

    for (int c = 0; c < NC; c++) {
        const int st = c & 1;
        {
            float4 ca0, ca1, cb0, cb1;
            ca0.x = to_tf32(pa0.x); ca0.y = to_tf32(pa0.y);
            ca0.z = to_tf32(pa0.z); ca0.w = to_tf32(pa0.w);
            ca1.x = to_tf32(pa1.x); ca1.y = to_tf32(pa1.y);
            ca1.z = to_tf32(pa1.z); ca1.w = to_tf32(pa1.w);
            cb0.x = to_tf32(pb0.x); cb0.y = to_tf32(pb0.y);
            cb0.z = to_tf32(pb0.z); cb0.w = to_tf32(pb0.w);
            cb1.x = to_tf32(pb1.x); cb1.y = to_tf32(pb1.y);
            cb1.z = to_tf32(pb1.z); cb1.w = to_tf32(pb1.w);
            *(float4*)&As[st][arow][acol]     = ca0;
            *(float4*)&As[st][arow][acol + 4] = ca1;
            *(float4*)&Bs[st][brow][bcol]     = cb0;
            *(float4*)&Bs[st][brow][bcol + 4] = cb1;
        }
        __syncthreads();

        if (c + 1 < NC) {
            const int k0 = (c + 1) << 4;
            pa0 = *(const float4*)(Ap + k0);
            pa1 = *(const float4*)(Ap + k0 + 4);
            pb0 = *(const float4*)(Bp + (size_t)k0 * N);
            pb1 = *(const float4*)(Bp + (size_t)k0 * N + 4);
        }

#pragma unroll
        for (int ks = 0; ks < 2; ks++) {
            const int kb = ks * 8;
            uint32_t af[2][4], bf[8][2];
#pragma unroll
            for (int mt = 0; mt < 2; mt++) {
                const int m = m0 + mt * 16 + g;
                af[mt][0] = __float_as_uint(As[st][m][kb + t]);
                af[mt][1] = __float_as_uint(As[st][m + 8][kb + t]);
                af[mt][2] = __float_as_uint(As[st][m][kb + t + 4]);
                af[mt][3] = __float_as_uint(As[st][m + 8][kb + t + 4]);
            }
#pragma unroll
            for (int nt = 0; nt < 8; nt++) {
                const int n = n0 + nt * 8 + g;
                bf[nt][0] = __float_as_uint(Bs[st][kb + t][n]);
                bf[nt][1] = __float_as_uint(Bs[st][kb + t + 4][n]);
            }
#pragma unroll
            for (int mt = 0; mt < 2; mt++)
#pragma unroll
                for (int nt = 0; nt < 8; nt++)
                    mma_tf32(acc[mt][nt][0], acc[mt][nt][1],
                             acc[mt][nt][2], acc[mt][nt][3],
                             af[mt][0], af[mt][1], af[mt][2], af[mt][3],
                             bf[nt][0], bf[nt][1]);
        }
        __syncthreads();
    }

    const int ng = bn + n0;
    if (MODE == 0) {
        const int which = ng >> 10;
        const int rem   = ng & 1023;
        const int h     = rem >> 6;
#pragma unroll
        for (int mt = 0; mt < 2; mt++) {
            const int row0 = bm + m0 + mt * 16 + g;
            const int row1 = row0 + 8;
            const int b0i = row0 >> 11, t0i = row0 & 2047;
            const int b1i = row1 >> 11, t1i = row1 & 2047;
            float* base0 = g_qkv + ((size_t)((which * BB + b0i) * NH + h) * TT + t0i) * HD;
            float* base1 = g_qkv + ((size_t)((which * BB + b1i) * NH + h) * TT + t1i) * HD;
#pragma unroll
            for (int nt = 0; nt < 8; nt++) {
                const int d = nt * 8 + 2 * t;
                const float bx = bias[ng + d], by = bias[ng + d + 1];
                float2 o0 = { acc[mt][nt][0] + bx, acc[mt][nt][1] + by };
                float2 o1 = { acc[mt][nt][2] + bx, acc[mt][nt][3] + by };
                *(float2*)(base0 + d) = o0;
                *(float2*)(base1 + d) = o1;
            }
        }
    } else {
#pragma unroll
        for (int mt = 0; mt < 2; mt++) {
            const int row0 = bm + m0 + mt * 16 + g;
            const int row1 = row0 + 8;
#pragma unroll
            for (int nt = 0; nt < 8; nt++) {
                const int n = ng + nt * 8 + 2 * t;
                const float bx = bias[n], by = bias[n + 1];
                float2 o0 = { acc[mt][nt][0] + bx, acc[mt][nt][1] + by };
                float2 o1 = { acc[mt][nt][2] + bx, acc[mt][nt][3] + by };
                *(float2*)(C + (size_t)row0 * N + n) = o0;
                *(float2*)(C + (size_t)row1 * N + n) = o1;
            }
        }
    }
}

// ---------------------------------------------------------------------------
// Flash attention on tf32 mma.sync.
// CTA: 128 q rows (8 warps x 16), key tiles of 64, online softmax.
// K[s][d] and V[s][d] row-major tiles ARE the col-major B operand of
// m16n8k8.row.col -> no transposes. Q held as register fragments (prescaled).
// P routed through padded smem (stride 68 -> all fragment LDS conflict-free).
// ---------------------------------------------------------------------------
#define FLASH_SMEM ((2 * 64 * 68 + 128 * 68) * 4)

__global__ __launch_bounds__(256) void flash_mma()
{
    extern __shared__ float sm[];
    float* Ks = sm;                  // [64][68] tf32
    float* Vs = sm + 64 * 68;        // [64][68] tf32
    float* Ps = sm + 2 * 64 * 68;    // [128][68]: Q staging, then P (tf32)

    const int tid  = threadIdx.x;
    const int w    = tid >> 5;
    const int lane = tid & 31;
    const int g    = lane >> 2;
    const int t    = lane & 3;
    const int qt   = (int)gridDim.x - 1 - (int)blockIdx.x;  // heavy CTAs first
    const int h    = blockIdx.y;
    const int b    = blockIdx.z;
    const int q_base = qt * 128;
    const int mb     = w * 16;

    const float* Qg = g_qkv + ((size_t)((0 * BB + b) * NH + h) * TT) * HD;
    const float* Kg = g_qkv + ((size_t)((1 * BB + b) * NH + h) * TT) * HD;
    const float* Vg = g_qkv + ((size_t)((2 * BB + b) * NH + h) * TT) * HD;

    // stage Q tile (prescaled by 1/sqrt(64), tf32-rounded)
    for (int i = tid; i < 2048; i += 256) {
        const int row = i >> 4, c4 = (i & 15) * 4;
        float4 v = *(const float4*)(Qg + (size_t)(q_base + row) * HD + c4);
        v.x = to_tf32(v.x * 0.125f);
        v.y = to_tf32(v.y * 0.125f);
        v.z = to_tf32(v.z * 0.125f);
        v.w = to_tf32(v.w * 0.125f);
        *(float4*)&Ps[row * 68 + c4] = v;
    }
    __syncthreads();

    // Q fragments in registers for the whole kernel
    uint32_t qa[8][4];
#pragma unroll
    for (int ks = 0; ks < 8; ks++) {
        const int kb = ks * 8;
        qa[ks][0] = __float_as_uint(Ps[(mb + g) * 68 + kb + t]);
        qa[ks][1] = __float_as_uint(Ps[(mb + g + 8) * 68 + kb + t]);
        qa[ks][2] = __float_as_uint(Ps[(mb + g) * 68 + kb + t + 4]);
        qa[ks][3] = __float_as_uint(Ps[(mb + g + 8) * 68 + kb + t + 4]);
    }

    float oacc[8][4];
#pragma unroll
    for (int nt = 0; nt < 8; nt++)
#pragma unroll
        for (int r = 0; r < 4; r++) oacc[nt][r] = 0.f;
    float m0 = -1e30f, m1 = -1e30f, l0 = 0.f, l1 = 0.f;
    const int r0 = q_base + mb + g, r1 = r0 + 8;

    const int nkt = 2 * qt + 2;
    for (int kt = 0; kt < nkt; kt++) {
        __syncthreads();   // prior-iteration Ks/Vs/Ps reads complete
        const float* Kt = Kg + (size_t)(kt * 64) * HD;
        const float* Vt = Vg + (size_t)(kt * 64) * HD;
        for (int i = tid; i < 1024; i += 256) {
            const int row = i >> 4, c4 = (i & 15) * 4;
            float4 kv = *(const float4*)(Kt + row * HD + c4);
            kv.x = to_tf32(kv.x); kv.y = to_tf32(kv.y);
            kv.z = to_tf32(kv.z); kv.w = to_tf32(kv.w);
            *(float4*)&Ks[row * 68 + c4] = kv;
            float4 vv = *(const float4*)(Vt + row * HD + c4);
            vv.x = to_tf32(vv.x); vv.y = to_tf32(vv.y);
            vv.z = to_tf32(vv.z); vv.w = to_tf32(vv.w);
            *(float4*)&Vs[row * 68 + c4] = vv;
        }
        __syncthreads();

        // S = Q @ K^T   (16x64 per warp)
        float sacc[8][4];
#pragma unroll
        for (int nt = 0; nt < 8; nt++)
#pragma unroll
            for (int r = 0; r < 4; r++) sacc[nt][r] = 0.f;
#pragma unroll
        for (int ks = 0; ks < 8; ks++) {
            const int kb = ks * 8;
            uint32_t bf[8][2];
#pragma unroll
            for (int nt = 0; nt < 8; nt++) {
                bf[nt][0] = __float_as_uint(Ks[(nt * 8 + g) * 68 + kb + t]);
                bf[nt][1] = __float_as_uint(Ks[(nt * 8 + g) * 68 + kb + t + 4]);
            }
#pragma unroll
            for (int nt = 0; nt < 8; nt++)
                mma_tf32(sacc[nt][0], sacc[nt][1], sacc[nt][2], sacc[nt][3],
                         qa[ks][0], qa[ks][1], qa[ks][2], qa[ks][3],
                         bf[nt][0], bf[nt][1]);
        }

        // causal mask (only the two diagonal tiles of this CTA)
        if (kt >= 2 * qt) {
            const int sb = kt * 64;
#pragma unroll
            for (int nt = 0; nt < 8; nt++) {
                const int c0 = sb + nt * 8 + 2 * t, c1 = c0 + 1;
                if (c0 > r0) sacc[nt][0] = -1e30f;
                if (c1 > r0) sacc[nt][1] = -1e30f;
                if (c0 > r1) sacc[nt][2] = -1e30f;
                if (c1 > r1) sacc[nt][3] = -1e30f;
            }
        }

        // online softmax
        float mx0 = -1e30f, mx1 = -1e30f;
#pragma unroll
        for (int nt = 0; nt < 8; nt++) {
            mx0 = fmaxf(mx0, fmaxf(sacc[nt][0], sacc[nt][1]));
            mx1 = fmaxf(mx1, fmaxf(sacc[nt][2], sacc[nt][3]));
        }
        mx0 = fmaxf(mx0, __shfl_xor_sync(0xffffffffu, mx0, 1));
        mx0 = fmaxf(mx0, __shfl_xor_sync(0xffffffffu, mx0, 2));
        mx1 = fmaxf(mx1, __shfl_xor_sync(0xffffffffu, mx1, 1));
        mx1 = fmaxf(mx1, __shfl_xor_sync(0xffffffffu, mx1, 2));

        const float mn0 = fmaxf(m0, mx0), mn1 = fmaxf(m1, mx1);
        const float f0 = __expf(m0 - mn0), f1 = __expf(m1 - mn1);
        float ls0 = 0.f, ls1 = 0.f;
#pragma unroll
        for (int nt = 0; nt < 8; nt++) {
            const float p00 = __expf(sacc[nt][0] - mn0);
            const float p01 = __expf(sacc[nt][1] - mn0);
            const float p10 = __expf(sacc[nt][2] - mn1);
            const float p11 = __expf(sacc[nt][3] - mn1);
            ls0 += p00 + p01;
            ls1 += p10 + p11;
            float2 s0 = { to_tf32(p00), to_tf32(p01) };
            float2 s1 = { to_tf32(p10), to_tf32(p11) };
            *(float2*)&Ps[(mb + g) * 68 + nt * 8 + 2 * t]     = s0;
            *(float2*)&Ps[(mb + g + 8) * 68 + nt * 8 + 2 * t] = s1;
        }
        ls0 += __shfl_xor_sync(0xffffffffu, ls0, 1);
        ls0 += __shfl_xor_sync(0xffffffffu, ls0, 2);
        ls1 += __shfl_xor_sync(0xffffffffu, ls1, 1);
        ls1 += __shfl_xor_sync(0xffffffffu, ls1, 2);
        l0 = l0 * f0 + ls0;
        l1 = l1 * f1 + ls1;
        m0 = mn0; m1 = mn1;
#pragma unroll
        for (int nt = 0; nt < 8; nt++) {
            oacc[nt][0] *= f0; oacc[nt][1] *= f0;
            oacc[nt][2] *= f1; oacc[nt][3] *= f1;
        }
        __syncwarp();   // P rows are private to this warp

        // O += P @ V
#pragma unroll
        for (int ks = 0; ks < 8; ks++) {
            const int kb = ks * 8;
            uint32_t pa[4];
            pa[0] = __float_as_uint(Ps[(mb + g) * 68 + kb + t]);
            pa[1] = __float_as_uint(Ps[(mb + g + 8) * 68 + kb + t]);
            pa[2] = __float_as_uint(Ps[(mb + g) * 68 + kb + t + 4]);
            pa[3] = __float_as_uint(Ps[(mb + g + 8) * 68 + kb + t + 4]);
            uint32_t bf[8][2];
#pragma unroll
            for (int nt = 0; nt < 8; nt++) {
                bf[nt][0] = __float_as_uint(Vs[(kb + t) * 68 + nt * 8 + g]);
                bf[nt][1] = __float_as_uint(Vs[(kb + t + 4) * 68 + nt * 8 + g]);
            }
#pragma unroll
            for (int nt = 0; nt < 8; nt++)
                mma_tf32(oacc[nt][0], oacc[nt][1], oacc[nt][2], oacc[nt][3],
                         pa[0], pa[1], pa[2], pa[3], bf[nt][0], bf[nt][1]);
        }
    }

    // epilogue
    const float i0 = 1.0f / l0, i1 = 1.0f / l1;
    float* O0 = g_att + ((size_t)(b * TT + r0) * NH + h) * HD;
    float* O1 = g_att + ((size_t)(b * TT + r1) * NH + h) * HD;
#pragma unroll
    for (int nt = 0; nt < 8; nt++) {
        const int d = nt * 8 + 2 * t;
        float2 o0 = { oacc[nt][0] * i0, oacc[nt][1] * i0 };
        float2 o1 = { oacc[nt][2] * i1, oacc[nt][3] * i1 };
        *(float2*)(O0 + d) = o0;
        *(float2*)(O1 + d) = o1;
    }
}

// ---------------------------------------------------------------------------
// kernel_launch
// ---------------------------------------------------------------------------
extern "C" void kernel_launch(void* const* d_in, const int* in_sizes, int n_in,
                              void* d_out, int out_size)
{
    const float* x      = (const float*)d_in[0];
    const float* w_qkv  = (const float*)d_in[1];
    const float* b_qkv  = (const float*)d_in[2];
    const float* w_proj = (const float*)d_in[3];
    const float* b_proj = (const float*)d_in[4];
    float* out = (float*)d_out;

    const int M = BB * TT;  // 4096

    cudaFuncSetAttribute(flash_mma, cudaFuncAttributeMaxDynamicSharedMemorySize,
                         FLASH_SMEM);

    // 1) QKV projection (tf32 mma.sync): [4096,1024] @ [1024,3072] -> g_qkv
    mma_gemm<0><<<dim3(3 * DM / 128, M / 128), 256>>>(x, w_qkv, b_qkv, nullptr, M, 3 * DM, DM);

    // 2) causal flash attention (tf32 mma.sync) -> g_att
    flash_mma<<<dim3(TT / 128, NH, BB), 256, FLASH_SMEM>>>();

    // 3) output projection (tf32 mma.sync) -> out
    mma_gemm<1><<<dim3(DM / 128, M / 128), 256>>>(nullptr, w_proj, b_proj, out, M, DM, DM);
}

// round 5
// speedup vs baseline: 2.6912x; 1.1188x over previous
#include <cuda_runtime.h>
#include <cstdint>

// Problem constants
#define DM   1024
#define NH   16
#define HD   64
#define BB   2
#define TT   2048

// Scratch (device globals: allocation-free rule)
__device__ float g_qkv[3 * BB * NH * TT * HD];   // [which][b][h][t][d]
__device__ float g_att[BB * TT * DM];            // [b][t][h][d] == [B*T, C]

// ---------------------------------------------------------------------------
// tf32 helpers (portable PTX: works on plain sm_103 target)
// ---------------------------------------------------------------------------
__device__ __forceinline__ float to_tf32(float x) {
    uint32_t u;
    asm("cvt.rna.tf32.f32 %0, %1;" : "=r"(u) : "f"(x));
    return __uint_as_float(u);
}
__device__ __forceinline__ uint32_t tf32u(float x) {
    uint32_t u;
    asm("cvt.rna.tf32.f32 %0, %1;" : "=r"(u) : "f"(x));
    return u;
}

__device__ __forceinline__ void mma_tf32(float& c0, float& c1, float& c2, float& c3,
                                         uint32_t a0, uint32_t a1, uint32_t a2, uint32_t a3,
                                         uint32_t b0, uint32_t b1) {
    asm volatile(
        "mma.sync.aligned.m16n8k8.row.col.f32.tf32.tf32.f32 "
        "{%0,%1,%2,%3}, {%4,%5,%6,%7}, {%8,%9}, {%0,%1,%2,%3};"
        : "+f"(c0), "+f"(c1), "+f"(c2), "+f"(c3)
        : "r"(a0), "r"(a1), "r"(a2), "r"(a3), "r"(b0), "r"(b1));
}

__device__ __forceinline__ uint32_t smem_u32(const void* p) {
    uint32_t a;
    asm("{ .reg .u64 t; cvta.to.shared.u64 t, %1; cvt.u32.u64 %0, t; }"
        : "=r"(a) : "l"(p));
    return a;
}
__device__ __forceinline__ void cpa16(uint32_t saddr, const void* g) {
    asm volatile("cp.async.cg.shared.global [%0], [%1], 16;"
                 :: "r"(saddr), "l"(g) : "memory");
}
#define CP_COMMIT() asm volatile("cp.async.commit_group;" ::: "memory")
#define CP_WAIT2()  asm volatile("cp.async.wait_group 2;" ::: "memory")

// ---------------------------------------------------------------------------
// tf32 tensor-core GEMM with 4-stage cp.async pipeline.
// C[M,N] = A[M,K] @ B[K,N] + bias[N].  BM=BN=128, BK=16, 8 warps (32x64 each).
// Raw fp32 staged to smem; cvt.rna.tf32 applied at fragment load.
// MODE 0: A = x, epilogue scatters into g_qkv.  MODE 1: A = g_att, plain C.
// ---------------------------------------------------------------------------
#define AS_STRIDE (128 * 20)      // floats per A stage
#define BS_STRIDE (16 * 136)      // floats per B stage
#define GSMEM_BYTES ((4 * AS_STRIDE + 4 * BS_STRIDE) * 4)

template <int MODE>
__global__ __launch_bounds__(256) void mma_gemm(const float* __restrict__ A,
                                                const float* __restrict__ Bw,
                                                const float* __restrict__ bias,
                                                float* __restrict__ C,
                                                int M, int N, int K)
{
    extern __shared__ float dsm[];
    float* AsF = dsm;                       // [4][128][20]
    float* BsF = dsm + 4 * AS_STRIDE;       // [4][16][136]
    const uint32_t abase = smem_u32(AsF);
    const uint32_t bbase = smem_u32(BsF);

    const int tid  = threadIdx.x;
    const int bm   = blockIdx.y * 128;
    const int bn   = blockIdx.x * 128;
    const int w    = tid >> 5;
    const int lane = tid & 31;
    const int g    = lane >> 2;
    const int t    = lane & 3;
    const int m0   = (w & 3) * 32;
    const int n0   = (w >> 2) * 64;

    const float* Aeff = (MODE == 0) ? A : (const float*)g_att;

    float acc[2][8][4];
#pragma unroll
    for (int mt = 0; mt < 2; mt++)
#pragma unroll
        for (int nt = 0; nt < 8; nt++)
#pragma unroll
            for (int r = 0; r < 4; r++) acc[mt][nt][r] = 0.f;

    // copy indexing: A chunk 128x16 = 512 float4 (2/thread); B chunk 16x128 same
    const int av0 = tid,        av1 = tid + 256;
    const int ar0 = av0 >> 2,   ac0 = (av0 & 3) * 4;
    const int ar1 = av1 >> 2,   ac1 = (av1 & 3) * 4;
    const int br0 = av0 >> 5,   bc0 = (av0 & 31) * 4;
    const int br1 = av1 >> 5,   bc1 = (av1 & 31) * 4;

    const int NC = K >> 4;

    auto issue = [&](int c) {
        const int s = c & 3;
        const uint32_t as = abase + (uint32_t)(s * AS_STRIDE) * 4u;
        const uint32_t bs = bbase + (uint32_t)(s * BS_STRIDE) * 4u;
        const int k0 = c << 4;
        cpa16(as + (uint32_t)(ar0 * 20 + ac0) * 4u,
              Aeff + (size_t)(bm + ar0) * K + k0 + ac0);
        cpa16(as + (uint32_t)(ar1 * 20 + ac1) * 4u,
              Aeff + (size_t)(bm + ar1) * K + k0 + ac1);
        cpa16(bs + (uint32_t)(br0 * 136 + bc0) * 4u,
              Bw + (size_t)(k0 + br0) * N + bn + bc0);
        cpa16(bs + (uint32_t)(br1 * 136 + bc1) * 4u,
              Bw + (size_t)(k0 + br1) * N + bn + bc1);
    };

    // prologue: stages 0..2 in flight
    issue(0); CP_COMMIT();
    issue(1); CP_COMMIT();
    issue(2); CP_COMMIT();

    for (int c = 0; c < NC; c++) {
        const int st = c & 3;
        CP_WAIT2();
        __syncthreads();          // chunk c visible to all; stage (c-1)&3 free

        if (c + 3 < NC) issue(c + 3);
        CP_COMMIT();              // commit (possibly empty) to keep counts aligned

        const float* As = AsF + st * AS_STRIDE;
        const float* Bs = BsF + st * BS_STRIDE;
#pragma unroll
        for (int ks = 0; ks < 2; ks++) {
            const int kb = ks * 8;
            uint32_t af[2][4], bf[8][2];
#pragma unroll
            for (int mt = 0; mt < 2; mt++) {
                const int m = m0 + mt * 16 + g;
                af[mt][0] = tf32u(As[m * 20 + kb + t]);
                af[mt][1] = tf32u(As[(m + 8) * 20 + kb + t]);
                af[mt][2] = tf32u(As[m * 20 + kb + t + 4]);
                af[mt][3] = tf32u(As[(m + 8) * 20 + kb + t + 4]);
            }
#pragma unroll
            for (int nt = 0; nt < 8; nt++) {
                const int n = n0 + nt * 8 + g;
                bf[nt][0] = tf32u(Bs[(kb + t) * 136 + n]);
                bf[nt][1] = tf32u(Bs[(kb + t + 4) * 136 + n]);
            }
#pragma unroll
            for (int mt = 0; mt < 2; mt++)
#pragma unroll
                for (int nt = 0; nt < 8; nt++)
                    mma_tf32(acc[mt][nt][0], acc[mt][nt][1],
                             acc[mt][nt][2], acc[mt][nt][3],
                             af[mt][0], af[mt][1], af[mt][2], af[mt][3],
                             bf[nt][0], bf[nt][1]);
        }
    }

    // ---- epilogue ----
    const int ng = bn + n0;
    if (MODE == 0) {
        const int which = ng >> 10;
        const int rem   = ng & 1023;
        const int h     = rem >> 6;
#pragma unroll
        for (int mt = 0; mt < 2; mt++) {
            const int row0 = bm + m0 + mt * 16 + g;
            const int row1 = row0 + 8;
            const int b0i = row0 >> 11, t0i = row0 & 2047;
            const int b1i = row1 >> 11, t1i = row1 & 2047;
            float* base0 = g_qkv + ((size_t)((which * BB + b0i) * NH + h) * TT + t0i) * HD;
            float* base1 = g_qkv + ((size_t)((which * BB + b1i) * NH + h) * TT + t1i) * HD;
#pragma unroll
            for (int nt = 0; nt < 8; nt++) {
                const int d = nt * 8 + 2 * t;
                const float bx = bias[ng + d], by = bias[ng + d + 1];
                float2 o0 = { acc[mt][nt][0] + bx, acc[mt][nt][1] + by };
                float2 o1 = { acc[mt][nt][2] + bx, acc[mt][nt][3] + by };
                *(float2*)(base0 + d) = o0;
                *(float2*)(base1 + d) = o1;
            }
        }
    } else {
#pragma unroll
        for (int mt = 0; mt < 2; mt++) {
            const int row0 = bm + m0 + mt * 16 + g;
            const int row1 = row0 + 8;
#pragma unroll
            for (int nt = 0; nt < 8; nt++) {
                const int n = ng + nt * 8 + 2 * t;
                const float bx = bias[n], by = bias[n + 1];
                float2 o0 = { acc[mt][nt][0] + bx, acc[mt][nt][1] + by };
                float2 o1 = { acc[mt][nt][2] + bx, acc[mt][nt][3] + by };
                *(float2*)(C + (size_t)row0 * N + n) = o0;
                *(float2*)(C + (size_t)row1 * N + n) = o1;
            }
        }
    }
}

// ---------------------------------------------------------------------------
// Flash attention on tf32 mma.sync (unchanged from R4).
// ---------------------------------------------------------------------------
#define FLASH_SMEM ((2 * 64 * 68 + 128 * 68) * 4)

__global__ __launch_bounds__(256) void flash_mma()
{
    extern __shared__ float sm[];
    float* Ks = sm;                  // [64][68] tf32
    float* Vs = sm + 64 * 68;        // [64][68] tf32
    float* Ps = sm + 2 * 64 * 68;    // [128][68]: Q staging, then P (tf32)

    const int tid  = threadIdx.x;
    const int w    = tid >> 5;
    const int lane = tid & 31;
    const int g    = lane >> 2;
    const int t    = lane & 3;
    const int qt   = (int)gridDim.x - 1 - (int)blockIdx.x;
    const int h    = blockIdx.y;
    const int b    = blockIdx.z;
    const int q_base = qt * 128;
    const int mb     = w * 16;

    const float* Qg = g_qkv + ((size_t)((0 * BB + b) * NH + h) * TT) * HD;
    const float* Kg = g_qkv + ((size_t)((1 * BB + b) * NH + h) * TT) * HD;
    const float* Vg = g_qkv + ((size_t)((2 * BB + b) * NH + h) * TT) * HD;

    for (int i = tid; i < 2048; i += 256) {
        const int row = i >> 4, c4 = (i & 15) * 4;
        float4 v = *(const float4*)(Qg + (size_t)(q_base + row) * HD + c4);
        v.x = to_tf32(v.x * 0.125f);
        v.y = to_tf32(v.y * 0.125f);
        v.z = to_tf32(v.z * 0.125f);
        v.w = to_tf32(v.w * 0.125f);
        *(float4*)&Ps[row * 68 + c4] = v;
    }
    __syncthreads();

    uint32_t qa[8][4];
#pragma unroll
    for (int ks = 0; ks < 8; ks++) {
        const int kb = ks * 8;
        qa[ks][0] = __float_as_uint(Ps[(mb + g) * 68 + kb + t]);
        qa[ks][1] = __float_as_uint(Ps[(mb + g + 8) * 68 + kb + t]);
        qa[ks][2] = __float_as_uint(Ps[(mb + g) * 68 + kb + t + 4]);
        qa[ks][3] = __float_as_uint(Ps[(mb + g + 8) * 68 + kb + t + 4]);
    }

    float oacc[8][4];
#pragma unroll
    for (int nt = 0; nt < 8; nt++)
#pragma unroll
        for (int r = 0; r < 4; r++) oacc[nt][r] = 0.f;
    float m0 = -1e30f, m1 = -1e30f, l0 = 0.f, l1 = 0.f;
    const int r0 = q_base + mb + g, r1 = r0 + 8;

    const int nkt = 2 * qt + 2;
    for (int kt = 0; kt < nkt; kt++) {
        __syncthreads();
        const float* Kt = Kg + (size_t)(kt * 64) * HD;
        const float* Vt = Vg + (size_t)(kt * 64) * HD;
        for (int i = tid; i < 1024; i += 256) {
            const int row = i >> 4, c4 = (i & 15) * 4;
            float4 kv = *(const float4*)(Kt + row * HD + c4);
            kv.x = to_tf32(kv.x); kv.y = to_tf32(kv.y);
            kv.z = to_tf32(kv.z); kv.w = to_tf32(kv.w);
            *(float4*)&Ks[row * 68 + c4] = kv;
            float4 vv = *(const float4*)(Vt + row * HD + c4);
            vv.x = to_tf32(vv.x); vv.y = to_tf32(vv.y);
            vv.z = to_tf32(vv.z); vv.w = to_tf32(vv.w);
            *(float4*)&Vs[row * 68 + c4] = vv;
        }
        __syncthreads();

        float sacc[8][4];
#pragma unroll
        for (int nt = 0; nt < 8; nt++)
#pragma unroll
            for (int r = 0; r < 4; r++) sacc[nt][r] = 0.f;
#pragma unroll
        for (int ks = 0; ks < 8; ks++) {
            const int kb = ks * 8;
            uint32_t bf[8][2];
#pragma unroll
            for (int nt = 0; nt < 8; nt++) {
                bf[nt][0] = __float_as_uint(Ks[(nt * 8 + g) * 68 + kb + t]);
                bf[nt][1] = __float_as_uint(Ks[(nt * 8 + g) * 68 + kb + t + 4]);
            }
#pragma unroll
            for (int nt = 0; nt < 8; nt++)
                mma_tf32(sacc[nt][0], sacc[nt][1], sacc[nt][2], sacc[nt][3],
                         qa[ks][0], qa[ks][1], qa[ks][2], qa[ks][3],
                         bf[nt][0], bf[nt][1]);
        }

        if (kt >= 2 * qt) {
            const int sb = kt * 64;
#pragma unroll
            for (int nt = 0; nt < 8; nt++) {
                const int c0 = sb + nt * 8 + 2 * t, c1 = c0 + 1;
                if (c0 > r0) sacc[nt][0] = -1e30f;
                if (c1 > r0) sacc[nt][1] = -1e30f;
                if (c0 > r1) sacc[nt][2] = -1e30f;
                if (c1 > r1) sacc[nt][3] = -1e30f;
            }
        }

        float mx0 = -1e30f, mx1 = -1e30f;
#pragma unroll
        for (int nt = 0; nt < 8; nt++) {
            mx0 = fmaxf(mx0, fmaxf(sacc[nt][0], sacc[nt][1]));
            mx1 = fmaxf(mx1, fmaxf(sacc[nt][2], sacc[nt][3]));
        }
        mx0 = fmaxf(mx0, __shfl_xor_sync(0xffffffffu, mx0, 1));
        mx0 = fmaxf(mx0, __shfl_xor_sync(0xffffffffu, mx0, 2));
        mx1 = fmaxf(mx1, __shfl_xor_sync(0xffffffffu, mx1, 1));
        mx1 = fmaxf(mx1, __shfl_xor_sync(0xffffffffu, mx1, 2));

        const float mn0 = fmaxf(m0, mx0), mn1 = fmaxf(m1, mx1);
        const float f0 = __expf(m0 - mn0), f1 = __expf(m1 - mn1);
        float ls0 = 0.f, ls1 = 0.f;
#pragma unroll
        for (int nt = 0; nt < 8; nt++) {
            const float p00 = __expf(sacc[nt][0] - mn0);
            const float p01 = __expf(sacc[nt][1] - mn0);
            const float p10 = __expf(sacc[nt][2] - mn1);
            const float p11 = __expf(sacc[nt][3] - mn1);
            ls0 += p00 + p01;
            ls1 += p10 + p11;
            float2 s0 = { to_tf32(p00), to_tf32(p01) };
            float2 s1 = { to_tf32(p10), to_tf32(p11) };
            *(float2*)&Ps[(mb + g) * 68 + nt * 8 + 2 * t]     = s0;
            *(float2*)&Ps[(mb + g + 8) * 68 + nt * 8 + 2 * t] = s1;
        }
        ls0 += __shfl_xor_sync(0xffffffffu, ls0, 1);
        ls0 += __shfl_xor_sync(0xffffffffu, ls0, 2);
        ls1 += __shfl_xor_sync(0xffffffffu, ls1, 1);
        ls1 += __shfl_xor_sync(0xffffffffu, ls1, 2);
        l0 = l0 * f0 + ls0;
        l1 = l1 * f1 + ls1;
        m0 = mn0; m1 = mn1;
#pragma unroll
        for (int nt = 0; nt < 8; nt++) {
            oacc[nt][0] *= f0; oacc[nt][1] *= f0;
            oacc[nt][2] *= f1; oacc[nt][3] *= f1;
        }
        __syncwarp();

#pragma unroll
        for (int ks = 0; ks < 8; ks++) {
            const int kb = ks * 8;
            uint32_t pa[4];
            pa[0] = __float_as_uint(Ps[(mb + g) * 68 + kb + t]);
            pa[1] = __float_as_uint(Ps[(mb + g + 8) * 68 + kb + t]);
            pa[2] = __float_as_uint(Ps[(mb + g) * 68 + kb + t + 4]);
            pa[3] = __float_as_uint(Ps[(mb + g + 8) * 68 + kb + t + 4]);
            uint32_t bf[8][2];
#pragma unroll
            for (int nt = 0; nt < 8; nt++) {
                bf[nt][0] = __float_as_uint(Vs[(kb + t) * 68 + nt * 8 + g]);
                bf[nt][1] = __float_as_uint(Vs[(kb + t + 4) * 68 + nt * 8 + g]);
            }
#pragma unroll
            for (int nt = 0; nt < 8; nt++)
                mma_tf32(oacc[nt][0], oacc[nt][1], oacc[nt][2], oacc[nt][3],
                         pa[0], pa[1], pa[2], pa[3], bf[nt][0], bf[nt][1]);
        }
    }

    const float i0 = 1.0f / l0, i1 = 1.0f / l1;
    float* O0 = g_att + ((size_t)(b * TT + r0) * NH + h) * HD;
    float* O1 = g_att + ((size_t)(b * TT + r1) * NH + h) * HD;
#pragma unroll
    for (int nt = 0; nt < 8; nt++) {
        const int d = nt * 8 + 2 * t;
        float2 o0 = { oacc[nt][0] * i0, oacc[nt][1] * i0 };
        float2 o1 = { oacc[nt][2] * i1, oacc[nt][3] * i1 };
        *(float2*)(O0 + d) = o0;
        *(float2*)(O1 + d) = o1;
    }
}

// ---------------------------------------------------------------------------
// kernel_launch
// ---------------------------------------------------------------------------
extern "C" void kernel_launch(void* const* d_in, const int* in_sizes, int n_in,
                              void* d_out, int out_size)
{
    const float* x      = (const float*)d_in[0];
    const float* w_qkv  = (const float*)d_in[1];
    const float* b_qkv  = (const float*)d_in[2];
    const float* w_proj = (const float*)d_in[3];
    const float* b_proj = (const float*)d_in[4];
    float* out = (float*)d_out;

    const int M = BB * TT;  // 4096

    cudaFuncSetAttribute(mma_gemm<0>, cudaFuncAttributeMaxDynamicSharedMemorySize, GSMEM_BYTES);
    cudaFuncSetAttribute(mma_gemm<1>, cudaFuncAttributeMaxDynamicSharedMemorySize, GSMEM_BYTES);
    cudaFuncSetAttribute(flash_mma, cudaFuncAttributeMaxDynamicSharedMemorySize, FLASH_SMEM);

    // 1) QKV projection (tf32 mma.sync + cp.async pipeline) -> g_qkv
    mma_gemm<0><<<dim3(3 * DM / 128, M / 128), 256, GSMEM_BYTES>>>(x, w_qkv, b_qkv, nullptr, M, 3 * DM, DM);

    // 2) causal flash attention (tf32 mma.sync) -> g_att
    flash_mma<<<dim3(TT / 128, NH, BB), 256, FLASH_SMEM>>>();

    // 3) output projection (tf32 mma.sync + cp.async pipeline) -> out
    mma_gemm<1><<<dim3(DM / 128, M / 128), 256, GSMEM_BYTES>>>(nullptr, w_proj, b_proj, out, M, DM, DM);
}